// round 16
// baseline (speedup 1.0000x reference)
#include <cuda_runtime.h>
#include <cstdint>

#define N_NODES 50000
#define CH 64

// sum-only accumulator (zeroed by memset node; x added during GEMM staging)
__device__ float4 g_agg4[N_NODES * (CH / 4)];

// ---------------------------------------------------------------------------
// Kernel 1: scatter-add. 8-lane group per edge; lane owns float4 j and j+8.
// (MLP=2 — proven optimum; at the LTS traffic floor)
// Edge-index dtype detected INLINE per warp (1 hot LDG + ballot).
// ---------------------------------------------------------------------------
__global__ void scatter_kernel(const float4* __restrict__ x4,
                               const void* __restrict__ ei_raw,
                               int nE) {
    const int* ei32 = (const int*)ei_raw;
    int wlane = threadIdx.x & 31;
    int bad = (ei32[2 * wlane + 1] != 0);
    unsigned m = __ballot_sync(0xFFFFFFFFu, bad);
    bool is64 = (m == 0u);

    int g = blockIdx.x * blockDim.x + threadIdx.x;
    int lane = g & 7;
    int edge = g >> 3;
    if (edge >= nE) return;

    long long src, dst;
    if (is64) {
        const long long* ei = (const long long*)ei_raw;
        src = ei[edge];
        dst = ei[nE + edge];
    } else {
        src = ei32[edge];
        dst = ei32[nE + edge];
    }
    if ((unsigned long long)src >= N_NODES || (unsigned long long)dst >= N_NODES)
        return;

    float4 v0 = x4[src * 16 + lane];
    float4 v1 = x4[src * 16 + lane + 8];
    float4* d0 = g_agg4 + dst * 16 + lane;
    float4* d1 = g_agg4 + dst * 16 + lane + 8;
    asm volatile("red.global.add.v4.f32 [%0], {%1, %2, %3, %4};"
                 :: "l"(d0), "f"(v0.x), "f"(v0.y), "f"(v0.z), "f"(v0.w)
                 : "memory");
    asm volatile("red.global.add.v4.f32 [%0], {%1, %2, %3, %4};"
                 :: "l"(d1), "f"(v1.x), "f"(v1.y), "f"(v1.z), "f"(v1.w)
                 : "memory");
}

// ---------------------------------------------------------------------------
// Kernel 2: out = relu((x + agg) @ W^T + b).
// GROWS=64, 256 threads, 4x4 per-thread tiles -> 782 blocks (~5.3 CTAs/SM).
// Rationale: both 8x8 and 8x4 configs plateaued at ~19us with ~2.6 CTAs/SM
// and no pipe >56% — stall/spread-bound. More concurrent CTAs + fewer
// front-batched LDGs per thread (20 vs 24+) overlap staging latency.
// ---------------------------------------------------------------------------
#define GROWS 64
#define GTHREADS 256
#define H_STRIDE4 17
#define WT_STRIDE 72
#define SMEM_BYTES ((GROWS * H_STRIDE4 * 4 + 64 * WT_STRIDE) * 4)

__device__ __forceinline__ unsigned long long splat_f32x2(float v) {
    unsigned long long d;
    unsigned u = __float_as_uint(v);
    asm("mov.b64 %0, {%1, %1};" : "=l"(d) : "r"(u));
    return d;
}
__device__ __forceinline__ unsigned long long pack_f32x2(float lo, float hi) {
    unsigned long long d;
    asm("mov.b64 %0, {%1, %2};" : "=l"(d) : "r"(__float_as_uint(lo)), "r"(__float_as_uint(hi)));
    return d;
}
#define FFMA2(acc, a, b) \
    asm("fma.rn.f32x2 %0, %1, %2, %0;" : "+l"(acc) : "l"(a), "l"(b))

__global__ void __launch_bounds__(GTHREADS) gemm_relu_kernel(
    const float4* __restrict__ x4,
    const float* __restrict__ W,
    const float* __restrict__ b,
    float* __restrict__ out)
{
    extern __shared__ float smem[];
    float4* sH4 = reinterpret_cast<float4*>(smem);              // [64][17] f4
    float*  sWT = smem + GROWS * H_STRIDE4 * 4;                 // [64][72]

    int t = threadIdx.x;
    int r0 = blockIdx.x * GROWS;

    // Stage W transposed (k-major): 4096 / 256 = 16 each
    #pragma unroll
    for (int k = 0; k < 16; k++) {
        int idx = t + k * 256;
        int o = idx >> 6;
        int i = idx & 63;
        sWT[i * WT_STRIDE + o] = W[idx];
    }
    // Stage h = x + agg, coalesced, swizzled: 1024 f4 / 256 = 4 each
    #pragma unroll
    for (int k = 0; k < 4; k++) {
        int idx = t + k * 256;
        int row = idx >> 4;          // 0..63
        int c4  = idx & 15;
        int grow = r0 + row;
        float4 v = make_float4(0.f, 0.f, 0.f, 0.f);
        if (grow < N_NODES) {
            float4 vx = x4[grow * 16 + c4];
            float4 va = g_agg4[grow * 16 + c4];
            v = make_float4(vx.x + va.x, vx.y + va.y, vx.z + va.z, vx.w + va.w);
        }
        int c4s = c4 ^ ((row >> 3) & 15);
        sH4[row * H_STRIDE4 + c4s] = v;
    }
    __syncthreads();

    int tr = t >> 4;         // 0..15 -> row group (4 rows)
    int tc = t & 15;         // 0..15 -> col group (4 cols)
    int rbase = tr * 4;
    int obase = tc * 4;
    int rsw = (rbase >> 3) & 15;     // same for all 4 rows of this group

    unsigned long long acc[4][2];
    {
        unsigned long long bp0 = pack_f32x2(b[obase],     b[obase + 1]);
        unsigned long long bp1 = pack_f32x2(b[obase + 2], b[obase + 3]);
        #pragma unroll
        for (int r = 0; r < 4; r++) { acc[r][0] = bp0; acc[r][1] = bp1; }
    }

    #pragma unroll 4
    for (int q = 0; q < 16; q++) {
        float4 hr[4];
        int qs = q ^ rsw;
        #pragma unroll
        for (int r = 0; r < 4; r++)
            hr[r] = sH4[(rbase + r) * H_STRIDE4 + qs];
        #pragma unroll
        for (int kk = 0; kk < 4; kk++) {
            int i = 4 * q + kk;
            ulonglong2 wP = *reinterpret_cast<const ulonglong2*>(&sWT[i * WT_STRIDE + obase]);
            #pragma unroll
            for (int r = 0; r < 4; r++) {
                float hv = (kk == 0) ? hr[r].x : (kk == 1) ? hr[r].y
                         : (kk == 2) ? hr[r].z : hr[r].w;
                unsigned long long h2 = splat_f32x2(hv);
                FFMA2(acc[r][0], h2, wP.x);
                FFMA2(acc[r][1], h2, wP.y);
            }
        }
    }

    #pragma unroll
    for (int r = 0; r < 4; r++) {
        int row = r0 + rbase + r;
        if (row < N_NODES) {
            float2 f0 = *reinterpret_cast<float2*>(&acc[r][0]);
            float2 f1 = *reinterpret_cast<float2*>(&acc[r][1]);
            float4 v = make_float4(fmaxf(f0.x, 0.f), fmaxf(f0.y, 0.f),
                                   fmaxf(f1.x, 0.f), fmaxf(f1.y, 0.f));
            *reinterpret_cast<float4*>(out + row * CH + obase) = v;
        }
    }
}

// ---------------------------------------------------------------------------
extern "C" void kernel_launch(void* const* d_in, const int* in_sizes, int n_in,
                              void* d_out, int out_size) {
    const float* x  = (const float*)d_in[0];
    const void*  ei = d_in[1];
    const float* W  = (const float*)d_in[2];
    const float* b  = (const float*)d_in[3];
    float* out = (float*)d_out;

    int nE = in_sizes[1] / 2;                 // 800000

    static bool attr_done = false;
    static void* agg_ptr = nullptr;
    if (!attr_done) {
        cudaFuncSetAttribute(gemm_relu_kernel,
                             cudaFuncAttributeMaxDynamicSharedMemorySize,
                             SMEM_BYTES);
        cudaGetSymbolAddress(&agg_ptr, g_agg4);
        attr_done = true;
    }

    cudaMemsetAsync(agg_ptr, 0, sizeof(float4) * N_NODES * (CH / 4));

    long long threads = (long long)nE * 8;
    int blocks = (int)((threads + 255) / 256);
    scatter_kernel<<<blocks, 256>>>(
        reinterpret_cast<const float4*>(x), ei, nE);

    int gblocks = (N_NODES + GROWS - 1) / GROWS;
    gemm_relu_kernel<<<gblocks, GTHREADS, SMEM_BYTES>>>(
        reinterpret_cast<const float4*>(x), W, b, out);
}